// round 8
// baseline (speedup 1.0000x reference)
#include <cuda_runtime.h>
#include <math.h>

// Problem constants
#define S_LEN 512
#define BATCH 64
#define DIM   512
#define HID   1024
#define G4H   4096          // 4*HID
#define KSPLIT 8
#define OUTN  1000
#define NBLK  256           // persistent grid size (<= 2 CTAs/SM * 148 SMs)

typedef unsigned long long ull;

// ---------------------------------------------------------------------------
// Device scratch (static __device__ globals only; no runtime allocation)
// ---------------------------------------------------------------------------
__device__ float g_XW0[(size_t)S_LEN * BATCH * G4H];   // 512 MB: x-part + biases per step
__device__ float g_gpart[KSPLIT * BATCH * G4H];        // 8 MB: split-K partials
__device__ float g_h[2][BATCH * HID];
__device__ float g_c[2][BATCH * HID];
__device__ unsigned g_bar_count;                        // software grid barrier
__device__ unsigned g_bar_gen;

// ---------------------------------------------------------------------------
// f32x2 packed-FMA helpers (Blackwell FFMA2 — only reachable via PTX)
// ---------------------------------------------------------------------------
__device__ __forceinline__ ull pack2(float v) {
    ull r;
    asm("mov.b64 %0, {%1, %1};" : "=l"(r) : "r"(__float_as_uint(v)));
    return r;
}
__device__ __forceinline__ void fma2(ull& acc, ull a, ull b) {
    asm("fma.rn.f32x2 %0, %1, %2, %0;" : "+l"(acc) : "l"(a), "l"(b));
}
__device__ __forceinline__ float2 unpack2(ull v) {
    unsigned lo, hi;
    asm("mov.b64 {%0, %1}, %2;" : "=r"(lo), "=r"(hi) : "l"(v));
    return make_float2(__uint_as_float(lo), __uint_as_float(hi));
}

// ---------------------------------------------------------------------------
// Shared GEMM tile core: C[64 x 128] += A[64 x 16*nch] * W[128 x 16*nch]^T
// 256 threads. tx = tid&31 (cols tx+32j, j<4), ty = tid>>5 (rows ty*8..+7).
// A rows broadcast per warp (all lanes same ty); W scalar loads conflict-free.
// Accumulators: 4 row-pairs x 4 cols of f32x2 (pairs over adjacent rows).
// ---------------------------------------------------------------------------
__device__ __forceinline__ void gemm_core(
    const float* __restrict__ arow,   // per-thread: A row lm, at kstart
    const float* __restrict__ wrow,   // per-thread: W row wr, at kstart+wks
    int nch,
    float As[2][16][72], float Ws[2][16][136],
    int tx, int ty, int lm, int lk, int wr, int wks,
    ull acc[4][4])
{
    // prologue: stage chunk 0
    {
        float4 va  = *(const float4*)(arow + lk);
        float4 vw0 = *(const float4*)(wrow);
        float4 vw1 = *(const float4*)(wrow + 4);
        As[0][lk+0][lm] = va.x;  As[0][lk+1][lm] = va.y;
        As[0][lk+2][lm] = va.z;  As[0][lk+3][lm] = va.w;
        Ws[0][wks+0][wr] = vw0.x; Ws[0][wks+1][wr] = vw0.y;
        Ws[0][wks+2][wr] = vw0.z; Ws[0][wks+3][wr] = vw0.w;
        Ws[0][wks+4][wr] = vw1.x; Ws[0][wks+5][wr] = vw1.y;
        Ws[0][wks+6][wr] = vw1.z; Ws[0][wks+7][wr] = vw1.w;
    }
    __syncthreads();

    for (int kc = 0; kc < nch; ++kc) {
        const int cur = kc & 1;
        float4 va, vw0, vw1;
        const bool more = (kc + 1 < nch);
        if (more) {
            const int k0 = (kc + 1) * 16;
            va  = *(const float4*)(arow + k0 + lk);
            vw0 = *(const float4*)(wrow + k0);
            vw1 = *(const float4*)(wrow + k0 + 4);
        }
#pragma unroll
        for (int kk = 0; kk < 16; ++kk) {
            ulonglong2 a01 = *(const ulonglong2*)&As[cur][kk][ty * 8];
            ulonglong2 a23 = *(const ulonglong2*)&As[cur][kk][ty * 8 + 4];
            const ull ap0 = a01.x, ap1 = a01.y, ap2 = a23.x, ap3 = a23.y;
#pragma unroll
            for (int j = 0; j < 4; ++j) {
                const ull w2 = pack2(Ws[cur][kk][tx + 32 * j]);
                fma2(acc[0][j], ap0, w2);
                fma2(acc[1][j], ap1, w2);
                fma2(acc[2][j], ap2, w2);
                fma2(acc[3][j], ap3, w2);
            }
        }
        if (more) {
            const int nb = cur ^ 1;
            As[nb][lk+0][lm] = va.x;  As[nb][lk+1][lm] = va.y;
            As[nb][lk+2][lm] = va.z;  As[nb][lk+3][lm] = va.w;
            Ws[nb][wks+0][wr] = vw0.x; Ws[nb][wks+1][wr] = vw0.y;
            Ws[nb][wks+2][wr] = vw0.z; Ws[nb][wks+3][wr] = vw0.w;
            Ws[nb][wks+4][wr] = vw1.x; Ws[nb][wks+5][wr] = vw1.y;
            Ws[nb][wks+6][wr] = vw1.z; Ws[nb][wks+7][wr] = vw1.w;
        }
        __syncthreads();
    }
}

// ---------------------------------------------------------------------------
// Init: copy h0/c0 into state buffers
// ---------------------------------------------------------------------------
__global__ void init_state_kernel(const float* __restrict__ h0,
                                  const float* __restrict__ c0) {
    int i = blockIdx.x * blockDim.x + threadIdx.x;
    if (i < 2 * BATCH * HID) {
        ((float*)g_h)[i] = h0[i];
        ((float*)g_c)[i] = c0[i];
    }
}

// ---------------------------------------------------------------------------
// Phase 1 (fully parallel): XW0[t] = x_t @ W_ih0^T + b_ih0 + b_hh0
// grid = (32 n-tiles of 128, 512 t), tile 64x128, K = 512 (32 chunks)
// ---------------------------------------------------------------------------
__global__ __launch_bounds__(256, 2) void xw0_kernel(
    const float* __restrict__ x, const float* __restrict__ Wih0,
    const float* __restrict__ b_ih0, const float* __restrict__ b_hh0)
{
    __shared__ float As[2][16][72];
    __shared__ float Ws[2][16][136];
    const int t   = blockIdx.y;
    const int n0  = blockIdx.x * 128;
    const int tid = threadIdx.x;
    const int tx = tid & 31, ty = tid >> 5;
    const int lm = tid >> 2, lk = (tid & 3) * 4;
    const int wr = tid >> 1, wks = (tid & 1) * 8;

    const float* arow = x + ((size_t)lm * S_LEN + t) * DIM;
    const float* wrow = Wih0 + (size_t)(n0 + wr) * DIM + wks;

    ull acc[4][4];
#pragma unroll
    for (int r = 0; r < 4; r++)
#pragma unroll
        for (int j = 0; j < 4; j++) acc[r][j] = 0ull;

    gemm_core(arow, wrow, DIM / 16, As, Ws, tx, ty, lm, lk, wr, wks, acc);

    float bias[4];
#pragma unroll
    for (int j = 0; j < 4; j++) {
        const int n = n0 + tx + 32 * j;
        bias[j] = b_ih0[n] + b_hh0[n];
    }
    float* op = g_XW0 + ((size_t)t * BATCH + ty * 8) * G4H + n0 + tx;
#pragma unroll
    for (int rp = 0; rp < 4; rp++)
#pragma unroll
        for (int j = 0; j < 4; j++) {
            float2 v = unpack2(acc[rp][j]);
            op[(size_t)(rp * 2 + 0) * G4H + 32 * j] = v.x + bias[j];
            op[(size_t)(rp * 2 + 1) * G4H + 32 * j] = v.y + bias[j];
        }
}

// ---------------------------------------------------------------------------
// Software grid barrier (all NBLK CTAs co-resident by construction)
// ---------------------------------------------------------------------------
__device__ __forceinline__ void grid_bar() {
    __syncthreads();
    if (threadIdx.x == 0) {
        __threadfence();
        const unsigned gen = *(volatile unsigned*)&g_bar_gen;
        if (atomicAdd(&g_bar_count, 1u) == NBLK - 1) {
            g_bar_count = 0;
            __threadfence();
            *(volatile unsigned*)&g_bar_gen = gen + 1;
        } else {
            while (*(volatile unsigned*)&g_bar_gen == gen) {}
        }
        __threadfence();
    }
    __syncthreads();
}

// ---------------------------------------------------------------------------
// Persistent recurrence kernel: 512 ticks, 4 phases/tick, software barriers.
// Virtual GEMM grid per phase: 32 n-tiles x KSPLIT=8 splits = 256 = NBLK.
//   L0: gates0 partials = h0_prev @ W_hh0^T            (K=1024, kchunk 128)
//   L1: gates1 partials = [h0_t, h1_prev] @ [Wih1,Whh1]^T (K=2048, kchunk 256)
// Cell phases: 65536 elems over 65536 threads.
// ---------------------------------------------------------------------------
__global__ __launch_bounds__(256, 2) void lstm_persistent_kernel(
    const float* __restrict__ W_hh0,
    const float* __restrict__ W_ih1, const float* __restrict__ W_hh1,
    const float* __restrict__ b_ih1, const float* __restrict__ b_hh1)
{
    __shared__ float As[2][16][72];
    __shared__ float Ws[2][16][136];
    const int tid = threadIdx.x;
    const int bid = blockIdx.x;
    const int tx = tid & 31, ty = tid >> 5;
    const int lm = tid >> 2, lk = (tid & 3) * 4;
    const int wr = tid >> 1, wks = (tid & 1) * 8;
    const int nt = bid & 31;          // n-tile
    const int ks = bid >> 5;          // k-split (0..7)
    const int n0 = nt * 128;

    // precomputed per-thread operand pointers
    // layer 0: kchunk 128
    const float* a0row = g_h[0] + (size_t)lm * HID + ks * 128;
    const float* w0row = W_hh0 + (size_t)(n0 + wr) * HID + ks * 128 + wks;
    // layer 1: kchunk 256; ks<4 -> h0 x W_ih1, ks>=4 -> h1 x W_hh1
    const int ks1 = (ks < 4) ? ks * 256 : (ks - 4) * 256;
    const float* a1base = (ks < 4) ? g_h[0] : g_h[1];
    const float* w1base = (ks < 4) ? W_ih1 : W_hh1;
    const float* a1row = a1base + (size_t)lm * HID + ks1;
    const float* w1row = w1base + (size_t)(n0 + wr) * HID + ks1 + wks;

    // cell-phase indexing
    const int cidx = bid * 256 + tid;         // 0..65535
    const int cm = cidx >> 10;
    const int cj = cidx & (HID - 1);

    float* gpart_out = g_gpart + ((size_t)(ks * BATCH) + ty * 8) * G4H + n0 + tx;

    for (int t = 0; t < S_LEN; ++t) {
        // ---- phase 1: layer-0 recurrent GEMM ----
        {
            ull acc[4][4];
#pragma unroll
            for (int r = 0; r < 4; r++)
#pragma unroll
                for (int j = 0; j < 4; j++) acc[r][j] = 0ull;
            gemm_core(a0row, w0row, 8, As, Ws, tx, ty, lm, lk, wr, wks, acc);
#pragma unroll
            for (int rp = 0; rp < 4; rp++)
#pragma unroll
                for (int j = 0; j < 4; j++) {
                    float2 v = unpack2(acc[rp][j]);
                    gpart_out[(size_t)(rp * 2 + 0) * G4H + 32 * j] = v.x;
                    gpart_out[(size_t)(rp * 2 + 1) * G4H + 32 * j] = v.y;
                }
        }
        grid_bar();

        // ---- phase 2: layer-0 cell update ----
        {
            float v[4];
#pragma unroll
            for (int g = 0; g < 4; g++) {
                const int n = g * HID + cj;
                float s = g_XW0[((size_t)t * BATCH + cm) * G4H + n];
#pragma unroll
                for (int ss = 0; ss < KSPLIT; ss++)
                    s += g_gpart[((size_t)(ss * BATCH) + cm) * G4H + n];
                v[g] = s;
            }
            const float ig = 1.0f / (1.0f + expf(-v[0]));
            const float fg = 1.0f / (1.0f + expf(-v[1]));
            const float gg = tanhf(v[2]);
            const float og = 1.0f / (1.0f + expf(-v[3]));
            const float c_new = fg * g_c[0][cidx] + ig * gg;
            g_c[0][cidx] = c_new;
            g_h[0][cidx] = og * tanhf(c_new);
        }
        grid_bar();

        // ---- phase 3: layer-1 GEMM (concat-K over [h0_t, h1_prev]) ----
        {
            ull acc[4][4];
#pragma unroll
            for (int r = 0; r < 4; r++)
#pragma unroll
                for (int j = 0; j < 4; j++) acc[r][j] = 0ull;
            gemm_core(a1row, w1row, 16, As, Ws, tx, ty, lm, lk, wr, wks, acc);
#pragma unroll
            for (int rp = 0; rp < 4; rp++)
#pragma unroll
                for (int j = 0; j < 4; j++) {
                    float2 v = unpack2(acc[rp][j]);
                    gpart_out[(size_t)(rp * 2 + 0) * G4H + 32 * j] = v.x;
                    gpart_out[(size_t)(rp * 2 + 1) * G4H + 32 * j] = v.y;
                }
        }
        grid_bar();

        // ---- phase 4: layer-1 cell update ----
        {
            float v[4];
#pragma unroll
            for (int g = 0; g < 4; g++) {
                const int n = g * HID + cj;
                float s = b_ih1[n] + b_hh1[n];
#pragma unroll
                for (int ss = 0; ss < KSPLIT; ss++)
                    s += g_gpart[((size_t)(ss * BATCH) + cm) * G4H + n];
                v[g] = s;
            }
            const float ig = 1.0f / (1.0f + expf(-v[0]));
            const float fg = 1.0f / (1.0f + expf(-v[1]));
            const float gg = tanhf(v[2]);
            const float og = 1.0f / (1.0f + expf(-v[3]));
            const float c_new = fg * g_c[1][cidx] + ig * gg;
            g_c[1][cidx] = c_new;
            g_h[1][cidx] = og * tanhf(c_new);
        }
        grid_bar();
    }
}

// ---------------------------------------------------------------------------
// Final FC: out = h1 @ W_fc^T + b_fc. One warp per output element.
// ---------------------------------------------------------------------------
__global__ void fc_kernel(const float* __restrict__ Wfc,
                          const float* __restrict__ bfc,
                          float* __restrict__ out)
{
    const int gwarp = (blockIdx.x * blockDim.x + threadIdx.x) >> 5;
    const int lane  = threadIdx.x & 31;
    if (gwarp >= BATCH * OUTN) return;
    const int m = gwarp / OUTN;
    const int o = gwarp % OUTN;
    const float* hp = g_h[1] + (size_t)m * HID;
    const float* wp = Wfc + (size_t)o * HID;
    float s = 0.0f;
#pragma unroll 8
    for (int k = lane; k < HID; k += 32) s += hp[k] * wp[k];
#pragma unroll
    for (int off = 16; off; off >>= 1) s += __shfl_xor_sync(0xffffffffu, s, off);
    if (lane == 0) out[m * OUTN + o] = s + bfc[o];
}

// ---------------------------------------------------------------------------
// Launch: exactly 4 graph nodes (init, xw0, persistent recurrence, fc).
// ---------------------------------------------------------------------------
extern "C" void kernel_launch(void* const* d_in, const int* in_sizes, int n_in,
                              void* d_out, int out_size) {
    const float* x      = (const float*)d_in[0];
    const float* h0     = (const float*)d_in[1];
    const float* c0     = (const float*)d_in[2];
    const float* W_ih0  = (const float*)d_in[3];
    const float* W_hh0  = (const float*)d_in[4];
    const float* b_ih0  = (const float*)d_in[5];
    const float* b_hh0  = (const float*)d_in[6];
    const float* W_ih1  = (const float*)d_in[7];
    const float* W_hh1  = (const float*)d_in[8];
    const float* b_ih1  = (const float*)d_in[9];
    const float* b_hh1  = (const float*)d_in[10];
    const float* W_fc   = (const float*)d_in[11];
    const float* b_fc   = (const float*)d_in[12];
    float* out = (float*)d_out;

    init_state_kernel<<<512, 256>>>(h0, c0);
    xw0_kernel<<<dim3(G4H / 128, S_LEN), 256>>>(x, W_ih0, b_ih0, b_hh0);
    lstm_persistent_kernel<<<NBLK, 256>>>(W_hh0, W_ih1, W_hh1, b_ih1, b_hh1);
    fc_kernel<<<(BATCH * OUTN + 7) / 8, 256>>>(W_fc, b_fc, out);
}

// round 9
// speedup vs baseline: 1.0225x; 1.0225x over previous
#include <cuda_runtime.h>
#include <math.h>

// Problem constants
#define S_LEN 512
#define BATCH 64
#define DIM   512
#define HID   1024
#define G4H   4096
#define KSPLIT 8
#define OUTN  1000
#define NBLK  256
#define BH    (BATCH * HID)

#define W_ELEMS ((size_t)G4H * HID)                    // 4M elems per big weight
#define OFF_HH0 ((size_t)0)
#define OFF_IH1 (W_ELEMS)
#define OFF_HH1 (2 * W_ELEMS)
#define OFF_IH0 (3 * W_ELEMS)                          // G4H x DIM
#define WTOT    (3 * W_ELEMS + (size_t)G4H * DIM)
#define XTOT    ((size_t)BATCH * S_LEN * DIM)

// dynamic smem layout (floats): Ab[64*68] As[64*68] Bb[128*68] Bs[128*68]
#define SA 4352
#define SB 8704
#define SMEM_BYTES ((2 * SA + 2 * SB) * 4)             // 104448 B

// ---------------------------------------------------------------------------
// Device scratch
// ---------------------------------------------------------------------------
__device__ float g_XW0[(size_t)S_LEN * BATCH * G4H];   // 512 MB x-part + biases
__device__ float g_Wb[WTOT];                           // tf32-big weights
__device__ float g_Ws[WTOT];                           // tf32-small weights
__device__ float g_xb[XTOT];
__device__ float g_xs[XTOT];
__device__ float g_gp0[(size_t)KSPLIT * BATCH * G4H];  // L0 split-K partials
__device__ float g_gp1[(size_t)KSPLIT * BATCH * G4H];  // L1 split-K partials
__device__ float g_h[2][BH];
__device__ float g_c[2][BH];
__device__ float g_hb[2][BH];                          // tf32-big h
__device__ float g_hs[2][BH];                          // tf32-small h
__device__ unsigned g_bar_count;
__device__ unsigned g_bar_gen;

// ---------------------------------------------------------------------------
// tf32 helpers
// ---------------------------------------------------------------------------
__device__ __forceinline__ float tf32_rna(float v) {
    unsigned r;
    asm("cvt.rna.tf32.f32 %0, %1;" : "=r"(r) : "f"(v));
    return __uint_as_float(r);
}

__device__ __forceinline__ void mma_tf32(float d[4],
                                         unsigned a0, unsigned a1, unsigned a2, unsigned a3,
                                         unsigned b0, unsigned b1) {
    asm("mma.sync.aligned.m16n8k8.row.col.f32.tf32.tf32.f32 "
        "{%0,%1,%2,%3}, {%4,%5,%6,%7}, {%8,%9}, {%0,%1,%2,%3};"
        : "+f"(d[0]), "+f"(d[1]), "+f"(d[2]), "+f"(d[3])
        : "r"(a0), "r"(a1), "r"(a2), "r"(a3), "r"(b0), "r"(b1));
}

// ---------------------------------------------------------------------------
// Warp-mma GEMM core: D[64 x 128] += A[64 x 64*nwin] * W[128 x 64*nwin]^T
// tf32x3: big*big + big*small + small*big (fp32-level accuracy).
// 256 threads = 8 warps; warp w owns n-cols [w*16, w*16+16), all 64 m-rows.
// ---------------------------------------------------------------------------
__device__ __forceinline__ void mma_gemm(
    const float* __restrict__ Agb, const float* __restrict__ Ags, size_t a_stride,
    const float* __restrict__ Wgb, const float* __restrict__ Wgs, size_t w_stride,
    int nwin, float d[4][2][4],
    float* sAb, float* sAs, float* sBb, float* sBs)
{
    const int tid  = threadIdx.x;
    const int warp = tid >> 5, lane = tid & 31;
    const int g = lane >> 2, tg = lane & 3;
    const int wn = warp * 16;
    const int sr = tid >> 4;           // staging row base 0..15
    const int sc = (tid & 15) * 4;     // staging col 0..60

    for (int w = 0; w < nwin; ++w) {
        const size_t koff = (size_t)w * 64;
        // stage A (64 x 64) big+small
#pragma unroll
        for (int i = 0; i < 4; i++) {
            const int r = sr + 16 * i;
            *(float4*)&sAb[r * 68 + sc] = *(const float4*)(Agb + (size_t)r * a_stride + koff + sc);
            *(float4*)&sAs[r * 68 + sc] = *(const float4*)(Ags + (size_t)r * a_stride + koff + sc);
        }
        // stage B (128 x 64) big+small
#pragma unroll
        for (int i = 0; i < 8; i++) {
            const int r = sr + 16 * i;
            *(float4*)&sBb[r * 68 + sc] = *(const float4*)(Wgb + (size_t)r * w_stride + koff + sc);
            *(float4*)&sBs[r * 68 + sc] = *(const float4*)(Wgs + (size_t)r * w_stride + koff + sc);
        }
        __syncthreads();

#pragma unroll
        for (int ks = 0; ks < 8; ++ks) {
            const int k0 = ks * 8 + tg;
            unsigned bb[2][2], bs[2][2];
#pragma unroll
            for (int nf = 0; nf < 2; nf++) {
                const int n = wn + nf * 8 + g;
                bb[nf][0] = __float_as_uint(sBb[n * 68 + k0]);
                bb[nf][1] = __float_as_uint(sBb[n * 68 + k0 + 4]);
                bs[nf][0] = __float_as_uint(sBs[n * 68 + k0]);
                bs[nf][1] = __float_as_uint(sBs[n * 68 + k0 + 4]);
            }
#pragma unroll
            for (int mf = 0; mf < 4; mf++) {
                const int r0 = mf * 16 + g;
                const unsigned ab0 = __float_as_uint(sAb[r0 * 68 + k0]);
                const unsigned ab1 = __float_as_uint(sAb[(r0 + 8) * 68 + k0]);
                const unsigned ab2 = __float_as_uint(sAb[r0 * 68 + k0 + 4]);
                const unsigned ab3 = __float_as_uint(sAb[(r0 + 8) * 68 + k0 + 4]);
                const unsigned as0 = __float_as_uint(sAs[r0 * 68 + k0]);
                const unsigned as1 = __float_as_uint(sAs[(r0 + 8) * 68 + k0]);
                const unsigned as2 = __float_as_uint(sAs[r0 * 68 + k0 + 4]);
                const unsigned as3 = __float_as_uint(sAs[(r0 + 8) * 68 + k0 + 4]);
#pragma unroll
                for (int nf = 0; nf < 2; nf++) {
                    mma_tf32(d[mf][nf], ab0, ab1, ab2, ab3, bb[nf][0], bb[nf][1]); // big*big
                    mma_tf32(d[mf][nf], ab0, ab1, ab2, ab3, bs[nf][0], bs[nf][1]); // big*small
                    mma_tf32(d[mf][nf], as0, as1, as2, as3, bb[nf][0], bb[nf][1]); // small*big
                }
            }
        }
        __syncthreads();
    }
}

// Store D frags to out[m][n_base + n], row stride = rstride
__device__ __forceinline__ void store_frags(float* __restrict__ out, int rstride,
                                            int n_base, float d[4][2][4]) {
    const int lane = threadIdx.x & 31, warp = threadIdx.x >> 5;
    const int g = lane >> 2, tg = lane & 3;
#pragma unroll
    for (int mf = 0; mf < 4; mf++)
#pragma unroll
        for (int nf = 0; nf < 2; nf++) {
            const int m = mf * 16 + g;
            const int n = n_base + warp * 16 + nf * 8 + 2 * tg;
            *(float2*)&out[(size_t)m * rstride + n]       = make_float2(d[mf][nf][0], d[mf][nf][1]);
            *(float2*)&out[(size_t)(m + 8) * rstride + n] = make_float2(d[mf][nf][2], d[mf][nf][3]);
        }
}

// ---------------------------------------------------------------------------
// Prelude: decompose weights and x into tf32 big/small
// ---------------------------------------------------------------------------
__global__ void decomp_kernel(const float* __restrict__ whh0, const float* __restrict__ wih1,
                              const float* __restrict__ whh1, const float* __restrict__ wih0,
                              const float* __restrict__ x) {
    const size_t stride = (size_t)gridDim.x * blockDim.x;
    const size_t total = WTOT + XTOT;
    for (size_t i = (size_t)blockIdx.x * blockDim.x + threadIdx.x; i < total; i += stride) {
        float v;
        float *db, *ds;
        if (i < WTOT) {
            size_t j = i;
            const float* src;
            if (j < W_ELEMS) src = whh0;
            else if (j < 2 * W_ELEMS) { src = wih1; j -= W_ELEMS; }
            else if (j < 3 * W_ELEMS) { src = whh1; j -= 2 * W_ELEMS; }
            else { src = wih0; j -= 3 * W_ELEMS; }
            v = src[j];
            db = &g_Wb[i]; ds = &g_Ws[i];
        } else {
            const size_t j = i - WTOT;
            v = x[j];
            db = &g_xb[j]; ds = &g_xs[j];
        }
        const float b = tf32_rna(v);
        *db = b;
        *ds = tf32_rna(v - b);
    }
}

__global__ void init_state_kernel(const float* __restrict__ h0,
                                  const float* __restrict__ c0) {
    const int i = blockIdx.x * blockDim.x + threadIdx.x;
    if (i < 2 * BH) {
        const float h = h0[i];
        ((float*)g_h)[i] = h;
        ((float*)g_c)[i] = c0[i];
        const float hb = tf32_rna(h);
        ((float*)g_hb)[i] = hb;
        ((float*)g_hs)[i] = tf32_rna(h - hb);
    }
}

// ---------------------------------------------------------------------------
// Prelude GEMM: XW0[t] = x_t @ W_ih0^T + b_ih0 + b_hh0   (tf32x3 mma)
// grid = (32 n-tiles, 512 t)
// ---------------------------------------------------------------------------
__global__ __launch_bounds__(256, 2) void xw0_mma_kernel(
    const float* __restrict__ b_ih0, const float* __restrict__ b_hh0)
{
    extern __shared__ float sm[];
    float *sAb = sm, *sAs = sm + SA, *sBb = sm + 2 * SA, *sBs = sm + 2 * SA + SB;
    const int nt = blockIdx.x, t = blockIdx.y;
    const int n0 = nt * 128;

    float d[4][2][4] = {};
    mma_gemm(g_xb + (size_t)t * DIM, g_xs + (size_t)t * DIM, (size_t)S_LEN * DIM,
             g_Wb + OFF_IH0 + (size_t)n0 * DIM, g_Ws + OFF_IH0 + (size_t)n0 * DIM, DIM,
             DIM / 64, d, sAb, sAs, sBb, sBs);

    // epilogue: + biases
    const int lane = threadIdx.x & 31, warp = threadIdx.x >> 5;
    const int g = lane >> 2, tg = lane & 3;
    float* out = g_XW0 + (size_t)t * BATCH * G4H;
#pragma unroll
    for (int nf = 0; nf < 2; nf++) {
        const int n = n0 + warp * 16 + nf * 8 + 2 * tg;
        const float bi0 = b_ih0[n] + b_hh0[n];
        const float bi1 = b_ih0[n + 1] + b_hh0[n + 1];
#pragma unroll
        for (int mf = 0; mf < 4; mf++) {
            const int m = mf * 16 + g;
            *(float2*)&out[(size_t)m * G4H + n] =
                make_float2(d[mf][nf][0] + bi0, d[mf][nf][1] + bi1);
            *(float2*)&out[(size_t)(m + 8) * G4H + n] =
                make_float2(d[mf][nf][2] + bi0, d[mf][nf][3] + bi1);
        }
    }
}

// ---------------------------------------------------------------------------
// Software grid barrier (256 CTAs co-resident: regs<=128, smem 2x104K fits)
// ---------------------------------------------------------------------------
__device__ __forceinline__ void grid_bar() {
    __syncthreads();
    if (threadIdx.x == 0) {
        __threadfence();
        const unsigned gen = *(volatile unsigned*)&g_bar_gen;
        if (atomicAdd(&g_bar_count, 1u) == NBLK - 1) {
            g_bar_count = 0;
            __threadfence();
            *(volatile unsigned*)&g_bar_gen = gen + 1;
        } else {
            while (*(volatile unsigned*)&g_bar_gen == gen) {}
        }
        __threadfence();
    }
    __syncthreads();
}

// ---------------------------------------------------------------------------
// LSTM cell math
// ---------------------------------------------------------------------------
__device__ __forceinline__ void cell_update(int layer, int cidx, float v0, float v1,
                                            float v2, float v3) {
    const float ig = 1.0f / (1.0f + expf(-v0));
    const float fg = 1.0f / (1.0f + expf(-v1));
    const float gg = tanhf(v2);
    const float og = 1.0f / (1.0f + expf(-v3));
    const float c_new = fg * g_c[layer][cidx] + ig * gg;
    g_c[layer][cidx] = c_new;
    const float h = og * tanhf(c_new);
    g_h[layer][cidx] = h;
    const float hb = tf32_rna(h);
    g_hb[layer][cidx] = hb;
    g_hs[layer][cidx] = tf32_rna(h - hb);
}

// ---------------------------------------------------------------------------
// Persistent recurrence: 2 phases/tick.
//  cell phase : cell0(t) + cell1(t-1)
//  gemm phase : L1GEMM(t) [h0(t),h1(t-1)] -> g_gp1 ; L0GEMM(t+1) [h0(t)] -> g_gp0
// ---------------------------------------------------------------------------
__global__ __launch_bounds__(256, 2) void lstm_persistent_kernel(
    const float* __restrict__ b_ih1, const float* __restrict__ b_hh1)
{
    extern __shared__ float sm[];
    float *sAb = sm, *sAs = sm + SA, *sBb = sm + 2 * SA, *sBs = sm + 2 * SA + SB;
    const int bid = blockIdx.x;
    const int nt = bid & 31, ks = bid >> 5;
    const int n0 = nt * 128;
    const int cidx = bid * 256 + threadIdx.x;
    const int cm = cidx >> 10, cj = cidx & (HID - 1);

    // prologue: L0 GEMM for t=0 (uses initial h0)
    {
        float d[4][2][4] = {};
        mma_gemm(g_hb[0] + ks * 128, g_hs[0] + ks * 128, HID,
                 g_Wb + OFF_HH0 + (size_t)n0 * HID + ks * 128,
                 g_Ws + OFF_HH0 + (size_t)n0 * HID + ks * 128, HID,
                 2, d, sAb, sAs, sBb, sBs);
        store_frags(g_gp0 + (size_t)ks * BATCH * G4H, G4H, n0, d);
    }
    grid_bar();

    for (int t = 0; t < S_LEN; ++t) {
        // ---- cell phase: cell0(t) (+ cell1(t-1)) ----
        {
            float v[4];
#pragma unroll
            for (int gt = 0; gt < 4; gt++) {
                const int n = gt * HID + cj;
                float s = g_XW0[((size_t)t * BATCH + cm) * G4H + n];
#pragma unroll
                for (int ss = 0; ss < KSPLIT; ss++)
                    s += g_gp0[((size_t)ss * BATCH + cm) * G4H + n];
                v[gt] = s;
            }
            cell_update(0, cidx, v[0], v[1], v[2], v[3]);

            if (t > 0) {
#pragma unroll
                for (int gt = 0; gt < 4; gt++) {
                    const int n = gt * HID + cj;
                    float s = b_ih1[n] + b_hh1[n];
#pragma unroll
                    for (int ss = 0; ss < KSPLIT; ss++)
                        s += g_gp1[((size_t)ss * BATCH + cm) * G4H + n];
                    v[gt] = s;
                }
                cell_update(1, cidx, v[0], v[1], v[2], v[3]);
            }
        }
        grid_bar();

        // ---- gemm phase ----
        {
            // L1 GEMM(t): A = [h0(t), h1(t-1)] split over k; K-chunk 256
            const float *Ab, *As, *Wb_, *Ws_;
            if (ks < 4) {
                Ab = g_hb[0] + ks * 256;  As = g_hs[0] + ks * 256;
                Wb_ = g_Wb + OFF_IH1 + (size_t)n0 * HID + ks * 256;
                Ws_ = g_Ws + OFF_IH1 + (size_t)n0 * HID + ks * 256;
            } else {
                Ab = g_hb[1] + (ks - 4) * 256;  As = g_hs[1] + (ks - 4) * 256;
                Wb_ = g_Wb + OFF_HH1 + (size_t)n0 * HID + (ks - 4) * 256;
                Ws_ = g_Ws + OFF_HH1 + (size_t)n0 * HID + (ks - 4) * 256;
            }
            {
                float d[4][2][4] = {};
                mma_gemm(Ab, As, HID, Wb_, Ws_, HID, 4, d, sAb, sAs, sBb, sBs);
                store_frags(g_gp1 + (size_t)ks * BATCH * G4H, G4H, n0, d);
            }
            // L0 GEMM(t+1): h0(t) @ W_hh0^T; K-chunk 128
            if (t + 1 < S_LEN) {
                float d[4][2][4] = {};
                mma_gemm(g_hb[0] + ks * 128, g_hs[0] + ks * 128, HID,
                         g_Wb + OFF_HH0 + (size_t)n0 * HID + ks * 128,
                         g_Ws + OFF_HH0 + (size_t)n0 * HID + ks * 128, HID,
                         2, d, sAb, sAs, sBb, sBs);
                store_frags(g_gp0 + (size_t)ks * BATCH * G4H, G4H, n0, d);
            }
        }
        grid_bar();
    }

    // final cell1(S_LEN-1); kernel boundary publishes h1 to fc
    {
        float v[4];
#pragma unroll
        for (int gt = 0; gt < 4; gt++) {
            const int n = gt * HID + cj;
            float s = b_ih1[n] + b_hh1[n];
#pragma unroll
            for (int ss = 0; ss < KSPLIT; ss++)
                s += g_gp1[((size_t)ss * BATCH + cm) * G4H + n];
            v[gt] = s;
        }
        cell_update(1, cidx, v[0], v[1], v[2], v[3]);
    }
}

// ---------------------------------------------------------------------------
// Final FC: out = h1 @ W_fc^T + b_fc
// ---------------------------------------------------------------------------
__global__ void fc_kernel(const float* __restrict__ Wfc,
                          const float* __restrict__ bfc,
                          float* __restrict__ out)
{
    const int gwarp = (blockIdx.x * blockDim.x + threadIdx.x) >> 5;
    const int lane  = threadIdx.x & 31;
    if (gwarp >= BATCH * OUTN) return;
    const int m = gwarp / OUTN;
    const int o = gwarp % OUTN;
    const float* hp = g_h[1] + (size_t)m * HID;
    const float* wp = Wfc + (size_t)o * HID;
    float s = 0.0f;
#pragma unroll 8
    for (int k = lane; k < HID; k += 32) s += hp[k] * wp[k];
#pragma unroll
    for (int off = 16; off; off >>= 1) s += __shfl_xor_sync(0xffffffffu, s, off);
    if (lane == 0) out[m * OUTN + o] = s + bfc[o];
}

// ---------------------------------------------------------------------------
// Launch: 5 graph nodes (decomp, init, xw0, persistent, fc)
// ---------------------------------------------------------------------------
extern "C" void kernel_launch(void* const* d_in, const int* in_sizes, int n_in,
                              void* d_out, int out_size) {
    const float* x      = (const float*)d_in[0];
    const float* h0     = (const float*)d_in[1];
    const float* c0     = (const float*)d_in[2];
    const float* W_ih0  = (const float*)d_in[3];
    const float* W_hh0  = (const float*)d_in[4];
    const float* b_ih0  = (const float*)d_in[5];
    const float* b_hh0  = (const float*)d_in[6];
    const float* W_ih1  = (const float*)d_in[7];
    const float* W_hh1  = (const float*)d_in[8];
    const float* b_ih1  = (const float*)d_in[9];
    const float* b_hh1  = (const float*)d_in[10];
    const float* W_fc   = (const float*)d_in[11];
    const float* b_fc   = (const float*)d_in[12];
    float* out = (float*)d_out;

    // idempotent attribute sets (host-side state, not stream ops)
    cudaFuncSetAttribute(xw0_mma_kernel,
                         cudaFuncAttributeMaxDynamicSharedMemorySize, SMEM_BYTES);
    cudaFuncSetAttribute(lstm_persistent_kernel,
                         cudaFuncAttributeMaxDynamicSharedMemorySize, SMEM_BYTES);

    decomp_kernel<<<4096, 256>>>(W_hh0, W_ih1, W_hh1, W_ih0, x);
    init_state_kernel<<<512, 256>>>(h0, c0);
    xw0_mma_kernel<<<dim3(32, S_LEN), 256, SMEM_BYTES>>>(b_ih0, b_hh0);
    lstm_persistent_kernel<<<NBLK, 256, SMEM_BYTES>>>(b_ih1, b_hh1);
    fc_kernel<<<(BATCH * OUTN + 7) / 8, 256>>>(W_fc, b_fc, out);
}

// round 13
// speedup vs baseline: 2.1350x; 2.0881x over previous
#include <cuda_runtime.h>
#include <cuda_bf16.h>
#include <cstdint>
#include <math.h>

// Problem constants
#define S_LEN 512
#define BATCH 64
#define DIM   512
#define HID   1024
#define G4H   4096
#define KSPLIT 8
#define OUTN  1000
#define NBLK  256
#define BH    (BATCH * HID)

#define W_ELEMS ((size_t)G4H * HID)
#define OFF_HH0 ((size_t)0)
#define OFF_IH1 (W_ELEMS)
#define OFF_HH1 (2 * W_ELEMS)
#define OFF_IH0 (3 * W_ELEMS)
#define WTOT    (3 * W_ELEMS + (size_t)G4H * DIM)
#define XTOT    ((size_t)BATCH * S_LEN * DIM)

// smem per buffer: Ahi 9216B | Alo 9216B | Bhi 18432B | Blo 18432B = 55296B
// double buffered -> 110592B  (2 CTAs/SM: 221184 + reserved <= 228KB)
#define A_LO_OFF 9216
#define B_HI_OFF 18432
#define B_LO_OFF 36864
#define BUFB     55296
#define SMEM_BYTES (2 * BUFB)
#define SLDB 144            // smem row stride in bytes (72 bf16: 64 data + 8 pad)

// ---------------------------------------------------------------------------
// Device scratch
// ---------------------------------------------------------------------------
__device__ float g_XW0[(size_t)S_LEN * BATCH * G4H];           // 512MB x-part + biases
__device__ __align__(16) __nv_bfloat16 g_Whi[WTOT];            // 28MB
__device__ __align__(16) __nv_bfloat16 g_Wlo[WTOT];            // 28MB
__device__ __align__(16) __nv_bfloat16 g_xhi[XTOT];            // 32MB
__device__ __align__(16) __nv_bfloat16 g_xlo[XTOT];            // 32MB
__device__ float g_gp0[(size_t)KSPLIT * BATCH * G4H];          // 8MB
__device__ float g_gp1[(size_t)KSPLIT * BATCH * G4H];          // 8MB
__device__ float g_h[2][BH];
__device__ float g_c[2][BH];
__device__ __align__(16) __nv_bfloat16 g_hhi[2][BH];
__device__ __align__(16) __nv_bfloat16 g_hlo[2][BH];
__device__ unsigned g_bar_count;
__device__ unsigned g_bar_gen;

// ---------------------------------------------------------------------------
// PTX wrappers
// ---------------------------------------------------------------------------
__device__ __forceinline__ void cpa16(uint32_t dst, const void* src) {
    asm volatile("cp.async.cg.shared.global [%0], [%1], 16;" :: "r"(dst), "l"(src));
}
#define CP_COMMIT() asm volatile("cp.async.commit_group;")
#define CP_WAIT(n)  asm volatile("cp.async.wait_group %0;" :: "n"(n))

__device__ __forceinline__ void ldmx4(unsigned& r0, unsigned& r1, unsigned& r2, unsigned& r3,
                                      uint32_t addr) {
    asm volatile("ldmatrix.sync.aligned.m8n8.x4.shared.b16 {%0,%1,%2,%3}, [%4];"
        : "=r"(r0), "=r"(r1), "=r"(r2), "=r"(r3) : "r"(addr));
}
__device__ __forceinline__ void ldmx2(unsigned& r0, unsigned& r1, uint32_t addr) {
    asm volatile("ldmatrix.sync.aligned.m8n8.x2.shared.b16 {%0,%1}, [%2];"
        : "=r"(r0), "=r"(r1) : "r"(addr));
}
__device__ __forceinline__ void mma_bf16(float d[4], const unsigned a[4], const unsigned b[2]) {
    asm volatile("mma.sync.aligned.m16n8k16.row.col.f32.bf16.bf16.f32 "
        "{%0,%1,%2,%3}, {%4,%5,%6,%7}, {%8,%9}, {%0,%1,%2,%3};"
        : "+f"(d[0]), "+f"(d[1]), "+f"(d[2]), "+f"(d[3])
        : "r"(a[0]), "r"(a[1]), "r"(a[2]), "r"(a[3]), "r"(b[0]), "r"(b[1]));
}

// ---------------------------------------------------------------------------
// Window staging: A[64 x 64] hi/lo + B[128 x 64] hi/lo, cp.async 16B chunks
// ---------------------------------------------------------------------------
__device__ __forceinline__ void stage_win(
    const __nv_bfloat16* __restrict__ Ahi, const __nv_bfloat16* __restrict__ Alo,
    size_t a_stride,
    const __nv_bfloat16* __restrict__ Bhi, const __nv_bfloat16* __restrict__ Blo,
    size_t b_stride, size_t koff, uint32_t buf)
{
    const int tid = threadIdx.x;
#pragma unroll
    for (int i = 0; i < 2; i++) {                 // A: 512 chunks (64 rows x 8)
        const int c = tid + 256 * i;
        const int row = c >> 3, cc = c & 7;
        const uint32_t d = buf + row * SLDB + cc * 16;
        const size_t g = (size_t)row * a_stride + koff + cc * 8;
        cpa16(d, Ahi + g);
        cpa16(d + A_LO_OFF, Alo + g);
    }
#pragma unroll
    for (int i = 0; i < 4; i++) {                 // B: 1024 chunks (128 rows x 8)
        const int c = tid + 256 * i;
        const int row = c >> 3, cc = c & 7;
        const uint32_t d = buf + B_HI_OFF + row * SLDB + cc * 16;
        const size_t g = (size_t)row * b_stride + koff + cc * 8;
        cpa16(d, Bhi + g);
        cpa16(d + (B_LO_OFF - B_HI_OFF), Blo + g);
    }
}

// ---------------------------------------------------------------------------
// Compute one staged window: D[64x128] += A * B^T (3-term bf16)
// ---------------------------------------------------------------------------
__device__ __forceinline__ void mma_win(uint32_t buf, uint32_t aoff, uint32_t boff,
                                        float d[4][2][4])
{
    const uint32_t Ah = buf, Al = buf + A_LO_OFF;
    const uint32_t Bh = buf + B_HI_OFF, Bl = buf + B_LO_OFF;
#pragma unroll
    for (int kq = 0; kq < 4; kq++) {
        unsigned bh[2][2], bl[2][2];
#pragma unroll
        for (int nf = 0; nf < 2; nf++) {
            ldmx2(bh[nf][0], bh[nf][1], Bh + nf * (8 * SLDB) + kq * 32 + boff);
            ldmx2(bl[nf][0], bl[nf][1], Bl + nf * (8 * SLDB) + kq * 32 + boff);
        }
#pragma unroll
        for (int mf = 0; mf < 4; mf++) {
            unsigned ah[4], al[4];
            ldmx4(ah[0], ah[1], ah[2], ah[3], Ah + mf * (16 * SLDB) + kq * 32 + aoff);
            ldmx4(al[0], al[1], al[2], al[3], Al + mf * (16 * SLDB) + kq * 32 + aoff);
#pragma unroll
            for (int nf = 0; nf < 2; nf++) {
                mma_bf16(d[mf][nf], ah, bh[nf]);   // hi*hi
                mma_bf16(d[mf][nf], ah, bl[nf]);   // hi*lo
                mma_bf16(d[mf][nf], al, bh[nf]);   // lo*hi
            }
        }
    }
}

// ---------------------------------------------------------------------------
// Full GEMM: D[64 x 128] += A[64 x 64*nwin] * W[128 x 64*nwin]^T
// cp.async double-buffered windows; 8 warps, warp owns 16 n-cols.
// ---------------------------------------------------------------------------
__device__ __forceinline__ void mma_gemm16(
    const __nv_bfloat16* __restrict__ Ahi, const __nv_bfloat16* __restrict__ Alo,
    size_t a_stride,
    const __nv_bfloat16* __restrict__ Bhi, const __nv_bfloat16* __restrict__ Blo,
    size_t b_stride, int nwin, float d[4][2][4], uint32_t smem_u)
{
    const int lane = threadIdx.x & 31, warp = threadIdx.x >> 5;
    // ldmatrix source row addresses:
    //  A x4: rows lane&15 within 16-row frag-pair, halves via lane>>4
    const uint32_t aoff = ((lane & 7) + ((lane >> 3) & 1) * 8) * SLDB + (lane >> 4) * 16;
    //  B x2: 16 rows of warp's n-strip, halves via (lane>>3)&1
    const uint32_t boff = (warp * 16 + (lane & 7)) * SLDB + ((lane >> 3) & 1) * 16;

    stage_win(Ahi, Alo, a_stride, Bhi, Blo, b_stride, 0, smem_u);
    CP_COMMIT();
#pragma unroll 1
    for (int w = 0; w < nwin; w++) {
        if (w + 1 < nwin) {
            stage_win(Ahi, Alo, a_stride, Bhi, Blo, b_stride,
                      (size_t)(w + 1) * 64, smem_u + ((w + 1) & 1) * BUFB);
            CP_COMMIT();
            CP_WAIT(1);
        } else {
            CP_WAIT(0);
        }
        __syncthreads();
        mma_win(smem_u + (w & 1) * BUFB, aoff, boff, d);
        __syncthreads();
    }
}

// Store D frags to out[m][n_base + n], row stride rstride
__device__ __forceinline__ void store_frags(float* __restrict__ out, int rstride,
                                            int n_base, float d[4][2][4]) {
    const int lane = threadIdx.x & 31, warp = threadIdx.x >> 5;
    const int g = lane >> 2, tg = lane & 3;
#pragma unroll
    for (int mf = 0; mf < 4; mf++)
#pragma unroll
        for (int nf = 0; nf < 2; nf++) {
            const int m = mf * 16 + g;
            const int n = n_base + warp * 16 + nf * 8 + 2 * tg;
            *(float2*)&out[(size_t)m * rstride + n]       = make_float2(d[mf][nf][0], d[mf][nf][1]);
            *(float2*)&out[(size_t)(m + 8) * rstride + n] = make_float2(d[mf][nf][2], d[mf][nf][3]);
        }
}

// ---------------------------------------------------------------------------
// Prelude: decompose weights and x into bf16 hi/lo
// ---------------------------------------------------------------------------
__global__ void decomp_kernel(const float* __restrict__ whh0, const float* __restrict__ wih1,
                              const float* __restrict__ whh1, const float* __restrict__ wih0,
                              const float* __restrict__ x) {
    const size_t stride = (size_t)gridDim.x * blockDim.x;
    const size_t total = WTOT + XTOT;
    for (size_t i = (size_t)blockIdx.x * blockDim.x + threadIdx.x; i < total; i += stride) {
        float v;
        __nv_bfloat16 *dh, *dl;
        if (i < WTOT) {
            size_t j = i;
            const float* src;
            if (j < W_ELEMS) src = whh0;
            else if (j < 2 * W_ELEMS) { src = wih1; j -= W_ELEMS; }
            else if (j < 3 * W_ELEMS) { src = whh1; j -= 2 * W_ELEMS; }
            else { src = wih0; j -= 3 * W_ELEMS; }
            v = src[j];
            dh = &g_Whi[i]; dl = &g_Wlo[i];
        } else {
            const size_t j = i - WTOT;
            v = x[j];
            dh = &g_xhi[j]; dl = &g_xlo[j];
        }
        const __nv_bfloat16 hi = __float2bfloat16_rn(v);
        *dh = hi;
        *dl = __float2bfloat16_rn(v - __bfloat162float(hi));
    }
}

__global__ void init_state_kernel(const float* __restrict__ h0,
                                  const float* __restrict__ c0) {
    const int i = blockIdx.x * blockDim.x + threadIdx.x;
    if (i < 2 * BH) {
        const float h = h0[i];
        ((float*)g_h)[i] = h;
        ((float*)g_c)[i] = c0[i];
        const __nv_bfloat16 hi = __float2bfloat16_rn(h);
        ((__nv_bfloat16*)g_hhi)[i] = hi;
        ((__nv_bfloat16*)g_hlo)[i] = __float2bfloat16_rn(h - __bfloat162float(hi));
    }
}

// ---------------------------------------------------------------------------
// Prelude GEMM: XW0[t] = x_t @ W_ih0^T + b_ih0 + b_hh0
// grid = (32 n-tiles, 512 t)
// ---------------------------------------------------------------------------
__global__ __launch_bounds__(256, 2) void xw0_mma_kernel(
    const float* __restrict__ b_ih0, const float* __restrict__ b_hh0)
{
    extern __shared__ char sm[];
    const uint32_t smem_u = (uint32_t)__cvta_generic_to_shared(sm);
    const int nt = blockIdx.x, t = blockIdx.y;
    const int n0 = nt * 128;

    float d[4][2][4] = {};
    mma_gemm16(g_xhi + (size_t)t * DIM, g_xlo + (size_t)t * DIM, (size_t)S_LEN * DIM,
               g_Whi + OFF_IH0 + (size_t)n0 * DIM, g_Wlo + OFF_IH0 + (size_t)n0 * DIM, DIM,
               DIM / 64, d, smem_u);

    const int lane = threadIdx.x & 31, warp = threadIdx.x >> 5;
    const int g = lane >> 2, tg = lane & 3;
    float* out = g_XW0 + (size_t)t * BATCH * G4H;
#pragma unroll
    for (int nf = 0; nf < 2; nf++) {
        const int n = n0 + warp * 16 + nf * 8 + 2 * tg;
        const float bi0 = b_ih0[n] + b_hh0[n];
        const float bi1 = b_ih0[n + 1] + b_hh0[n + 1];
#pragma unroll
        for (int mf = 0; mf < 4; mf++) {
            const int m = mf * 16 + g;
            *(float2*)&out[(size_t)m * G4H + n] =
                make_float2(d[mf][nf][0] + bi0, d[mf][nf][1] + bi1);
            *(float2*)&out[(size_t)(m + 8) * G4H + n] =
                make_float2(d[mf][nf][2] + bi0, d[mf][nf][3] + bi1);
        }
    }
}

// ---------------------------------------------------------------------------
// Software grid barrier (256 CTAs, 2/SM guaranteed by launch_bounds + smem)
// ---------------------------------------------------------------------------
__device__ __forceinline__ void grid_bar() {
    __syncthreads();
    if (threadIdx.x == 0) {
        __threadfence();
        const unsigned gen = *(volatile unsigned*)&g_bar_gen;
        if (atomicAdd(&g_bar_count, 1u) == NBLK - 1) {
            g_bar_count = 0;
            __threadfence();
            *(volatile unsigned*)&g_bar_gen = gen + 1;
        } else {
            while (*(volatile unsigned*)&g_bar_gen == gen) {}
        }
        __threadfence();
    }
    __syncthreads();
}

// ---------------------------------------------------------------------------
// LSTM cell math (also refreshes bf16 hi/lo of h)
// ---------------------------------------------------------------------------
__device__ __forceinline__ void cell_update(int layer, int cidx, float v0, float v1,
                                            float v2, float v3) {
    const float ig = 1.0f / (1.0f + expf(-v0));
    const float fg = 1.0f / (1.0f + expf(-v1));
    const float gg = tanhf(v2);
    const float og = 1.0f / (1.0f + expf(-v3));
    const float c_new = fg * g_c[layer][cidx] + ig * gg;
    g_c[layer][cidx] = c_new;
    const float h = og * tanhf(c_new);
    g_h[layer][cidx] = h;
    const __nv_bfloat16 hi = __float2bfloat16_rn(h);
    g_hhi[layer][cidx] = hi;
    g_hlo[layer][cidx] = __float2bfloat16_rn(h - __bfloat162float(hi));
}

// ---------------------------------------------------------------------------
// Persistent recurrence: 2 phases/tick.
//  cell phase : cell0(t) + cell1(t-1)
//  gemm phase : L1GEMM(t) -> g_gp1 ; L0GEMM(t+1) -> g_gp0
// ---------------------------------------------------------------------------
__global__ __launch_bounds__(256, 2) void lstm_persistent_kernel(
    const float* __restrict__ b_ih1, const float* __restrict__ b_hh1)
{
    extern __shared__ char sm[];
    const uint32_t smem_u = (uint32_t)__cvta_generic_to_shared(sm);
    const int bid = blockIdx.x;
    const int nt = bid & 31, ks = bid >> 5;
    const int n0 = nt * 128;
    const int cidx = bid * 256 + threadIdx.x;
    const int cm = cidx >> 10, cj = cidx & (HID - 1);

    // L1 operand mapping (kchunk 256): ks<4 -> h0 x W_ih1, ks>=4 -> h1 x W_hh1
    const int ks1 = (ks < 4) ? ks * 256 : (ks - 4) * 256;
    const int l1layer = (ks < 4) ? 0 : 1;
    const size_t l1w = ((ks < 4) ? OFF_IH1 : OFF_HH1) + (size_t)n0 * HID + ks1;

    // prologue: L0 GEMM for t=0
    {
        float d[4][2][4] = {};
        mma_gemm16(g_hhi[0] + ks * 128, g_hlo[0] + ks * 128, HID,
                   g_Whi + OFF_HH0 + (size_t)n0 * HID + ks * 128,
                   g_Wlo + OFF_HH0 + (size_t)n0 * HID + ks * 128, HID,
                   2, d, smem_u);
        store_frags(g_gp0 + (size_t)ks * BATCH * G4H, G4H, n0, d);
    }
    grid_bar();

    for (int t = 0; t < S_LEN; ++t) {
        // ---- cell phase ----
        {
            float v[4];
#pragma unroll
            for (int gt = 0; gt < 4; gt++) {
                const int n = gt * HID + cj;
                float s = g_XW0[((size_t)t * BATCH + cm) * G4H + n];
#pragma unroll
                for (int ss = 0; ss < KSPLIT; ss++)
                    s += g_gp0[((size_t)ss * BATCH + cm) * G4H + n];
                v[gt] = s;
            }
            cell_update(0, cidx, v[0], v[1], v[2], v[3]);

            if (t > 0) {
#pragma unroll
                for (int gt = 0; gt < 4; gt++) {
                    const int n = gt * HID + cj;
                    float s = b_ih1[n] + b_hh1[n];
#pragma unroll
                    for (int ss = 0; ss < KSPLIT; ss++)
                        s += g_gp1[((size_t)ss * BATCH + cm) * G4H + n];
                    v[gt] = s;
                }
                cell_update(1, cidx, v[0], v[1], v[2], v[3]);
            }
        }
        grid_bar();

        // ---- gemm phase ----
        {
            float d[4][2][4] = {};
            mma_gemm16(g_hhi[l1layer] + ks1, g_hlo[l1layer] + ks1, HID,
                       g_Whi + l1w, g_Wlo + l1w, HID, 4, d, smem_u);
            store_frags(g_gp1 + (size_t)ks * BATCH * G4H, G4H, n0, d);
        }
        if (t + 1 < S_LEN) {
            float d[4][2][4] = {};
            mma_gemm16(g_hhi[0] + ks * 128, g_hlo[0] + ks * 128, HID,
                       g_Whi + OFF_HH0 + (size_t)n0 * HID + ks * 128,
                       g_Wlo + OFF_HH0 + (size_t)n0 * HID + ks * 128, HID,
                       2, d, smem_u);
            store_frags(g_gp0 + (size_t)ks * BATCH * G4H, G4H, n0, d);
        }
        grid_bar();
    }

    // final cell1(S_LEN-1)
    {
        float v[4];
#pragma unroll
        for (int gt = 0; gt < 4; gt++) {
            const int n = gt * HID + cj;
            float s = b_ih1[n] + b_hh1[n];
#pragma unroll
            for (int ss = 0; ss < KSPLIT; ss++)
                s += g_gp1[((size_t)ss * BATCH + cm) * G4H + n];
            v[gt] = s;
        }
        cell_update(1, cidx, v[0], v[1], v[2], v[3]);
    }
}

// ---------------------------------------------------------------------------
// Final FC: out = h1 @ W_fc^T + b_fc
// ---------------------------------------------------------------------------
__global__ void fc_kernel(const float* __restrict__ Wfc,
                          const float* __restrict__ bfc,
                          float* __restrict__ out)
{
    const int gwarp = (blockIdx.x * blockDim.x + threadIdx.x) >> 5;
    const int lane  = threadIdx.x & 31;
    if (gwarp >= BATCH * OUTN) return;
    const int m = gwarp / OUTN;
    const int o = gwarp % OUTN;
    const float* hp = g_h[1] + (size_t)m * HID;
    const float* wp = Wfc + (size_t)o * HID;
    float s = 0.0f;
#pragma unroll 8
    for (int k = lane; k < HID; k += 32) s += hp[k] * wp[k];
#pragma unroll
    for (int off = 16; off; off >>= 1) s += __shfl_xor_sync(0xffffffffu, s, off);
    if (lane == 0) out[m * OUTN + o] = s + bfc[o];
}

// ---------------------------------------------------------------------------
// Launch: 5 graph nodes
// ---------------------------------------------------------------------------
extern "C" void kernel_launch(void* const* d_in, const int* in_sizes, int n_in,
                              void* d_out, int out_size) {
    const float* x      = (const float*)d_in[0];
    const float* h0     = (const float*)d_in[1];
    const float* c0     = (const float*)d_in[2];
    const float* W_ih0  = (const float*)d_in[3];
    const float* W_hh0  = (const float*)d_in[4];
    const float* b_ih0  = (const float*)d_in[5];
    const float* b_hh0  = (const float*)d_in[6];
    const float* W_ih1  = (const float*)d_in[7];
    const float* W_hh1  = (const float*)d_in[8];
    const float* b_ih1  = (const float*)d_in[9];
    const float* b_hh1  = (const float*)d_in[10];
    const float* W_fc   = (const float*)d_in[11];
    const float* b_fc   = (const float*)d_in[12];
    float* out = (float*)d_out;

    cudaFuncSetAttribute(xw0_mma_kernel,
                         cudaFuncAttributeMaxDynamicSharedMemorySize, SMEM_BYTES);
    cudaFuncSetAttribute(lstm_persistent_kernel,
                         cudaFuncAttributeMaxDynamicSharedMemorySize, SMEM_BYTES);

    decomp_kernel<<<4096, 256>>>(W_hh0, W_ih1, W_hh1, W_ih0, x);
    init_state_kernel<<<512, 256>>>(h0, c0);
    xw0_mma_kernel<<<dim3(32, S_LEN), 256, SMEM_BYTES>>>(b_ih0, b_hh0);
    lstm_persistent_kernel<<<NBLK, 256, SMEM_BYTES>>>(b_ih1, b_hh1);
    fc_kernel<<<(BATCH * OUTN + 7) / 8, 256>>>(W_fc, b_fc, out);
}